// round 1
// baseline (speedup 1.0000x reference)
#include <cuda_runtime.h>
#include <cstdint>

#define M_B 128
#define N_F 1024
#define K_F 1024
#define KSPLIT 8
#define BN 64
#define KT 32
#define KCHUNK (K_F / KSPLIT)   /* 128 */

// Scratch (device globals: no allocation allowed in kernel_launch)
__device__ float g_partial[KSPLIT * M_B * N_F];   // 4 MB split-K partials
__device__ float g_v[M_B * 2];                    // v[b,p] = (input_b . A) . codes_b
__device__ float g_d[M_B * 2];                    // diag(codes_b)

// ---------------------------------------------------------------------------
// Kernel 1: per-batch low-rank coefficients
//   u[b,r] = sum_i input[b,i] * A[i,r]
//   v[b,p] = sum_r u[b,r] * codes[b,r,p]
//   d[b,r] = codes[b,r,r]
// ---------------------------------------------------------------------------
__global__ void prep_kernel(const float* __restrict__ input,
                            const float* __restrict__ codes,
                            const float* __restrict__ A) {
    int b = blockIdx.x;
    int t = threadIdx.x;
    float p0 = 0.f, p1 = 0.f;
    const float* in_row = input + b * K_F;
    for (int i = t; i < K_F; i += 128) {
        float x = in_row[i];
        p0 += x * A[i * 2 + 0];
        p1 += x * A[i * 2 + 1];
    }
    __shared__ float s0[128], s1[128];
    s0[t] = p0; s1[t] = p1;
    __syncthreads();
    for (int s = 64; s > 0; s >>= 1) {
        if (t < s) { s0[t] += s0[t + s]; s1[t] += s1[t + s]; }
        __syncthreads();
    }
    if (t == 0) {
        float u0 = s0[0], u1 = s1[0];
        float c00 = codes[b * 4 + 0], c01 = codes[b * 4 + 1];
        float c10 = codes[b * 4 + 2], c11 = codes[b * 4 + 3];
        g_v[b * 2 + 0] = u0 * c00 + u1 * c10;
        g_v[b * 2 + 1] = u0 * c01 + u1 * c11;
        g_d[b * 2 + 0] = c00;
        g_d[b * 2 + 1] = c11;
    }
}

// ---------------------------------------------------------------------------
// Kernel 2: split-K tf32 tensor-core GEMM  partial[ks] = input @ weight[kchunk]
// Block tile: 128(M) x 64(N), K chunk 128, staged in KT=32 slices.
// 256 threads = 8 warps in 4(m) x 2(n) grid, warp tile 32x32 via m16n8k8.
// ---------------------------------------------------------------------------
__device__ __forceinline__ uint32_t f2tf32(float x) {
    uint32_t r;
    asm("cvt.rna.tf32.f32 %0, %1;" : "=r"(r) : "f"(x));
    return r;
}

__global__ __launch_bounds__(256) void gemm_kernel(
        const float* __restrict__ input, const float* __restrict__ weight) {
    // strides chosen bank-conflict-free for both fragment loads and f4 stores
    __shared__ float sA[128][KT + 4];   // stride 36: (4g+q) mod 32 all distinct
    __shared__ float sB[KT][BN + 8];    // stride 72: (8q+g) mod 32 all distinct

    int tid = threadIdx.x;
    int nb = blockIdx.x * BN;
    int ks = blockIdx.y;
    int k_base = ks * KCHUNK;

    int wid = tid >> 5, lane = tid & 31;
    int wm = wid & 3, wn = wid >> 2;
    int m_base = wm * 32, n_base = wn * 32;
    int g = lane >> 2, q = lane & 3;

    float acc[2][4][4];
    #pragma unroll
    for (int mi = 0; mi < 2; mi++)
        #pragma unroll
        for (int ni = 0; ni < 4; ni++)
            #pragma unroll
            for (int r = 0; r < 4; r++) acc[mi][ni][r] = 0.f;

    for (int s = 0; s < KCHUNK / KT; s++) {
        int k0 = k_base + s * KT;
        // load input tile 128 x KT (float4, fully coalesced)
        #pragma unroll
        for (int t = 0; t < 4; t++) {
            int idx = tid + t * 256;
            int row = idx >> 3, c4 = (idx & 7) * 4;
            float4 v = *reinterpret_cast<const float4*>(input + row * K_F + k0 + c4);
            *reinterpret_cast<float4*>(&sA[row][c4]) = v;
        }
        // load weight tile KT x BN
        #pragma unroll
        for (int t = 0; t < 2; t++) {
            int idx = tid + t * 256;
            int row = idx >> 4, c4 = (idx & 15) * 4;
            float4 v = *reinterpret_cast<const float4*>(weight + (k0 + row) * N_F + nb + c4);
            *reinterpret_cast<float4*>(&sB[row][c4]) = v;
        }
        __syncthreads();
        #pragma unroll
        for (int kk = 0; kk < KT; kk += 8) {
            uint32_t afr[2][4], bfr[4][2];
            #pragma unroll
            for (int mi = 0; mi < 2; mi++) {
                int r0 = m_base + mi * 16 + g;
                afr[mi][0] = f2tf32(sA[r0    ][kk + q    ]);
                afr[mi][1] = f2tf32(sA[r0 + 8][kk + q    ]);
                afr[mi][2] = f2tf32(sA[r0    ][kk + q + 4]);
                afr[mi][3] = f2tf32(sA[r0 + 8][kk + q + 4]);
            }
            #pragma unroll
            for (int ni = 0; ni < 4; ni++) {
                int c0 = n_base + ni * 8 + g;
                bfr[ni][0] = f2tf32(sB[kk + q    ][c0]);
                bfr[ni][1] = f2tf32(sB[kk + q + 4][c0]);
            }
            #pragma unroll
            for (int mi = 0; mi < 2; mi++)
                #pragma unroll
                for (int ni = 0; ni < 4; ni++) {
                    asm volatile(
                        "mma.sync.aligned.m16n8k8.row.col.f32.tf32.tf32.f32 "
                        "{%0,%1,%2,%3}, {%4,%5,%6,%7}, {%8,%9}, {%0,%1,%2,%3};\n"
                        : "+f"(acc[mi][ni][0]), "+f"(acc[mi][ni][1]),
                          "+f"(acc[mi][ni][2]), "+f"(acc[mi][ni][3])
                        : "r"(afr[mi][0]), "r"(afr[mi][1]),
                          "r"(afr[mi][2]), "r"(afr[mi][3]),
                          "r"(bfr[ni][0]), "r"(bfr[ni][1]));
                }
        }
        __syncthreads();
    }
    // write split-K partials
    float* part = g_partial + ks * (M_B * N_F);
    #pragma unroll
    for (int mi = 0; mi < 2; mi++)
        #pragma unroll
        for (int ni = 0; ni < 4; ni++) {
            int row = m_base + mi * 16 + g;
            int col = nb + n_base + ni * 8 + q * 2;
            part[row * N_F + col]           = acc[mi][ni][0];
            part[row * N_F + col + 1]       = acc[mi][ni][1];
            part[(row + 8) * N_F + col]     = acc[mi][ni][2];
            part[(row + 8) * N_F + col + 1] = acc[mi][ni][3];
        }
}

// ---------------------------------------------------------------------------
// Kernel 3: split-K reduction + full epilogue
//   out[b,j] = sum_ks partial + bias[j] + v[b,:].B[:,j] + d[b,:].bias_context[:,j]
// ---------------------------------------------------------------------------
__global__ void reduce_kernel(float* __restrict__ out,
                              const float* __restrict__ Bm,
                              const float* __restrict__ bias,
                              const float* __restrict__ bctx) {
    int idx = blockIdx.x * blockDim.x + threadIdx.x;  // 0 .. 131071
    int b = idx >> 10, j = idx & 1023;
    float s = 0.f;
    #pragma unroll
    for (int ks = 0; ks < KSPLIT; ks++) s += g_partial[ks * (M_B * N_F) + idx];
    float v0 = g_v[b * 2], v1 = g_v[b * 2 + 1];
    float d0 = g_d[b * 2], d1 = g_d[b * 2 + 1];
    out[idx] = s + bias[j]
             + v0 * Bm[j] + v1 * Bm[N_F + j]
             + d0 * bctx[j] + d1 * bctx[N_F + j];
}

extern "C" void kernel_launch(void* const* d_in, const int* in_sizes, int n_in,
                              void* d_out, int out_size) {
    const float* input  = (const float*)d_in[0];
    const float* codes  = (const float*)d_in[1];
    const float* weight = (const float*)d_in[2];
    const float* A      = (const float*)d_in[3];
    const float* Bm     = (const float*)d_in[4];
    const float* bias   = (const float*)d_in[5];
    const float* bctx   = (const float*)d_in[6];
    float* out = (float*)d_out;

    prep_kernel<<<M_B, 128>>>(input, codes, A);
    gemm_kernel<<<dim3(N_F / BN, KSPLIT), 256>>>(input, weight);
    reduce_kernel<<<(M_B * N_F) / 256, 256>>>(out, Bm, bias, bctx);
}

// round 2
// speedup vs baseline: 1.1080x; 1.1080x over previous
#include <cuda_runtime.h>
#include <cstdint>

#define M_B 128
#define N_F 1024
#define K_F 1024
#define KSPLIT 4
#define BN 32
#define KT 32
#define KCHUNK (K_F / KSPLIT)      /* 256 */
#define NITER (KCHUNK / KT)        /* 8 */

// Scratch (device globals: no allocation allowed in kernel_launch)
__device__ float g_partial[KSPLIT * M_B * N_F];   // 2 MB split-K partials
__device__ float g_v[M_B * 2];                    // v[b,p] = (input_b . A) . codes_b
__device__ float g_d[M_B * 2];                    // diag(codes_b)

// ---------------------------------------------------------------------------
// cp.async helpers
// ---------------------------------------------------------------------------
__device__ __forceinline__ void cp_async16(void* smem, const void* gmem) {
    uint32_t s = (uint32_t)__cvta_generic_to_shared(smem);
    asm volatile("cp.async.cg.shared.global [%0], [%1], 16;\n" :: "r"(s), "l"(gmem));
}
__device__ __forceinline__ void cp_commit() {
    asm volatile("cp.async.commit_group;\n");
}
template <int N>
__device__ __forceinline__ void cp_wait() {
    asm volatile("cp.async.wait_group %0;\n" :: "n"(N));
}

// ---------------------------------------------------------------------------
// Kernel 1: per-batch low-rank coefficients (one memory round-trip)
//   u[b,r] = sum_i input[b,i] * A[i,r];  v = u . codes_b;  d = diag(codes_b)
// 128 blocks x 256 threads: thread t owns input[b, 4t..4t+3].
// ---------------------------------------------------------------------------
__global__ __launch_bounds__(256) void prep_kernel(
        const float* __restrict__ input,
        const float* __restrict__ codes,
        const float* __restrict__ A) {
    int b = blockIdx.x;
    int t = threadIdx.x;

    float4 x = *reinterpret_cast<const float4*>(input + b * K_F + t * 4);
    const float2* A2 = reinterpret_cast<const float2*>(A);
    float2 a0 = A2[t * 4 + 0];
    float2 a1 = A2[t * 4 + 1];
    float2 a2 = A2[t * 4 + 2];
    float2 a3 = A2[t * 4 + 3];

    float p0 = x.x * a0.x + x.y * a1.x + x.z * a2.x + x.w * a3.x;
    float p1 = x.x * a0.y + x.y * a1.y + x.z * a2.y + x.w * a3.y;

    // warp reduce
    #pragma unroll
    for (int off = 16; off > 0; off >>= 1) {
        p0 += __shfl_xor_sync(0xFFFFFFFFu, p0, off);
        p1 += __shfl_xor_sync(0xFFFFFFFFu, p1, off);
    }
    __shared__ float s0[8], s1[8];
    int w = t >> 5, lane = t & 31;
    if (lane == 0) { s0[w] = p0; s1[w] = p1; }
    __syncthreads();
    if (t == 0) {
        float u0 = 0.f, u1 = 0.f;
        #pragma unroll
        for (int i = 0; i < 8; i++) { u0 += s0[i]; u1 += s1[i]; }
        float c00 = codes[b * 4 + 0], c01 = codes[b * 4 + 1];
        float c10 = codes[b * 4 + 2], c11 = codes[b * 4 + 3];
        g_v[b * 2 + 0] = u0 * c00 + u1 * c10;
        g_v[b * 2 + 1] = u0 * c01 + u1 * c11;
        g_d[b * 2 + 0] = c00;
        g_d[b * 2 + 1] = c11;
    }
}

// ---------------------------------------------------------------------------
// Kernel 2: split-K tf32 tensor GEMM with 2-stage cp.async pipeline.
// Block tile 128(M) x 32(N), K chunk 256 in KT=32 slices.
// 8 warps: 4(m) x 2(n); warp tile 32x16 via m16n8k8 (mi=2, ni=2).
// ---------------------------------------------------------------------------
__device__ __forceinline__ uint32_t f2tf32(float x) {
    uint32_t r;
    asm("cvt.rna.tf32.f32 %0, %1;" : "=r"(r) : "f"(x));
    return r;
}

__global__ __launch_bounds__(256) void gemm_kernel(
        const float* __restrict__ input, const float* __restrict__ weight) {
    // bank-conflict-free strides (verified for both f4 stores and frag loads)
    __shared__ float sA[2][128][KT + 4];   // stride 36
    __shared__ float sB[2][KT][BN + 8];    // stride 40

    int tid = threadIdx.x;
    int nb = blockIdx.x * BN;
    int ks = blockIdx.y;
    int k_base = ks * KCHUNK;

    int wid = tid >> 5, lane = tid & 31;
    int wm = wid & 3, wn = wid >> 2;
    int m_base = wm * 32, n_base = wn * 16;
    int g = lane >> 2, q = lane & 3;

    // per-thread load coordinates
    int a_row = tid >> 3, a_c4 = (tid & 7) * 4;   // + t*256 rows per iter
    int b_row = tid >> 3, b_c4 = (tid & 7) * 4;   // exactly 256 f4 = full tile

    float acc[2][2][4];
    #pragma unroll
    for (int mi = 0; mi < 2; mi++)
        #pragma unroll
        for (int ni = 0; ni < 2; ni++)
            #pragma unroll
            for (int r = 0; r < 4; r++) acc[mi][ni][r] = 0.f;

    // ---- prefetch stage 0 ----
    {
        int k0 = k_base;
        #pragma unroll
        for (int t = 0; t < 4; t++) {
            int row = a_row + t * 32;
            cp_async16(&sA[0][row][a_c4], input + row * K_F + k0 + a_c4);
        }
        cp_async16(&sB[0][b_row][b_c4], weight + (k0 + b_row) * N_F + nb + b_c4);
        cp_commit();
    }

    for (int s = 0; s < NITER; s++) {
        int buf = s & 1;
        if (s + 1 < NITER) {
            int k0 = k_base + (s + 1) * KT;
            int nbuf = (s + 1) & 1;
            #pragma unroll
            for (int t = 0; t < 4; t++) {
                int row = a_row + t * 32;
                cp_async16(&sA[nbuf][row][a_c4], input + row * K_F + k0 + a_c4);
            }
            cp_async16(&sB[nbuf][b_row][b_c4], weight + (k0 + b_row) * N_F + nb + b_c4);
            cp_commit();
            cp_wait<1>();
        } else {
            cp_wait<0>();
        }
        __syncthreads();

        #pragma unroll
        for (int kk = 0; kk < KT; kk += 8) {
            uint32_t afr[2][4], bfr[2][2];
            #pragma unroll
            for (int mi = 0; mi < 2; mi++) {
                int r0 = m_base + mi * 16 + g;
                afr[mi][0] = f2tf32(sA[buf][r0    ][kk + q    ]);
                afr[mi][1] = f2tf32(sA[buf][r0 + 8][kk + q    ]);
                afr[mi][2] = f2tf32(sA[buf][r0    ][kk + q + 4]);
                afr[mi][3] = f2tf32(sA[buf][r0 + 8][kk + q + 4]);
            }
            #pragma unroll
            for (int ni = 0; ni < 2; ni++) {
                int c0 = n_base + ni * 8 + g;
                bfr[ni][0] = f2tf32(sB[buf][kk + q    ][c0]);
                bfr[ni][1] = f2tf32(sB[buf][kk + q + 4][c0]);
            }
            #pragma unroll
            for (int mi = 0; mi < 2; mi++)
                #pragma unroll
                for (int ni = 0; ni < 2; ni++) {
                    asm volatile(
                        "mma.sync.aligned.m16n8k8.row.col.f32.tf32.tf32.f32 "
                        "{%0,%1,%2,%3}, {%4,%5,%6,%7}, {%8,%9}, {%0,%1,%2,%3};\n"
                        : "+f"(acc[mi][ni][0]), "+f"(acc[mi][ni][1]),
                          "+f"(acc[mi][ni][2]), "+f"(acc[mi][ni][3])
                        : "r"(afr[mi][0]), "r"(afr[mi][1]),
                          "r"(afr[mi][2]), "r"(afr[mi][3]),
                          "r"(bfr[ni][0]), "r"(bfr[ni][1]));
                }
        }
        __syncthreads();
    }

    // write split-K partials
    float* part = g_partial + ks * (M_B * N_F);
    #pragma unroll
    for (int mi = 0; mi < 2; mi++)
        #pragma unroll
        for (int ni = 0; ni < 2; ni++) {
            int row = m_base + mi * 16 + g;
            int col = nb + n_base + ni * 8 + q * 2;
            part[row * N_F + col]           = acc[mi][ni][0];
            part[row * N_F + col + 1]       = acc[mi][ni][1];
            part[(row + 8) * N_F + col]     = acc[mi][ni][2];
            part[(row + 8) * N_F + col + 1] = acc[mi][ni][3];
        }
}

// ---------------------------------------------------------------------------
// Kernel 3: split-K reduction + full epilogue (float4 vectorized)
//   out[b,j] = sum_ks partial + bias[j] + v[b,:].B[:,j] + d[b,:].bias_context[:,j]
// ---------------------------------------------------------------------------
__global__ __launch_bounds__(256) void reduce_kernel(
        float* __restrict__ out,
        const float* __restrict__ Bm,
        const float* __restrict__ bias,
        const float* __restrict__ bctx) {
    int idx4 = blockIdx.x * blockDim.x + threadIdx.x;   // 0 .. 32767 (float4s)
    int b = idx4 >> 8;          // 256 float4 per row
    int j4 = (idx4 & 255) * 4;  // float index within row

    float4 s = *reinterpret_cast<const float4*>(&g_partial[idx4 * 4]);
    #pragma unroll
    for (int ks = 1; ks < KSPLIT; ks++) {
        float4 p = *reinterpret_cast<const float4*>(
            &g_partial[ks * (M_B * N_F) + idx4 * 4]);
        s.x += p.x; s.y += p.y; s.z += p.z; s.w += p.w;
    }
    float v0 = g_v[b * 2], v1 = g_v[b * 2 + 1];
    float d0 = g_d[b * 2], d1 = g_d[b * 2 + 1];

    float4 bi  = *reinterpret_cast<const float4*>(bias + j4);
    float4 B0  = *reinterpret_cast<const float4*>(Bm + j4);
    float4 B1  = *reinterpret_cast<const float4*>(Bm + N_F + j4);
    float4 c0  = *reinterpret_cast<const float4*>(bctx + j4);
    float4 c1  = *reinterpret_cast<const float4*>(bctx + N_F + j4);

    float4 o;
    o.x = s.x + bi.x + v0 * B0.x + v1 * B1.x + d0 * c0.x + d1 * c1.x;
    o.y = s.y + bi.y + v0 * B0.y + v1 * B1.y + d0 * c0.y + d1 * c1.y;
    o.z = s.z + bi.z + v0 * B0.z + v1 * B1.z + d0 * c0.z + d1 * c1.z;
    o.w = s.w + bi.w + v0 * B0.w + v1 * B1.w + d0 * c0.w + d1 * c1.w;
    *reinterpret_cast<float4*>(out + idx4 * 4) = o;
}

extern "C" void kernel_launch(void* const* d_in, const int* in_sizes, int n_in,
                              void* d_out, int out_size) {
    const float* input  = (const float*)d_in[0];
    const float* codes  = (const float*)d_in[1];
    const float* weight = (const float*)d_in[2];
    const float* A      = (const float*)d_in[3];
    const float* Bm     = (const float*)d_in[4];
    const float* bias   = (const float*)d_in[5];
    const float* bctx   = (const float*)d_in[6];
    float* out = (float*)d_out;

    prep_kernel<<<M_B, 256>>>(input, codes, A);
    gemm_kernel<<<dim3(N_F / BN, KSPLIT), 256>>>(input, weight);
    reduce_kernel<<<(M_B * N_F / 4) / 256, 256>>>(out, Bm, bias, bctx);
}

// round 3
// speedup vs baseline: 1.2857x; 1.1604x over previous
#include <cuda_runtime.h>
#include <cstdint>

#define M_B 128
#define N_F 1024
#define K_F 1024
#define KSPLIT 4
#define BN 32
#define KT 32
#define KCHUNK (K_F / KSPLIT)      /* 256 */
#define NITER (KCHUNK / KT)        /* 8 */
#define GRID 128                   /* 32 nb-blocks x 4 ks — single wave on 148 SMs */

// Scratch (device globals: no allocation allowed in kernel_launch)
__device__ float g_partial[KSPLIT * M_B * N_F];   // 2 MB split-K partials
__device__ unsigned int g_cnt = 0;                 // monotonic ticket barrier

// ---------------------------------------------------------------------------
// cp.async helpers
// ---------------------------------------------------------------------------
__device__ __forceinline__ void cp_async16(void* smem, const void* gmem) {
    uint32_t s = (uint32_t)__cvta_generic_to_shared(smem);
    asm volatile("cp.async.cg.shared.global [%0], [%1], 16;\n" :: "r"(s), "l"(gmem));
}
__device__ __forceinline__ void cp_commit() {
    asm volatile("cp.async.commit_group;\n");
}
template <int N>
__device__ __forceinline__ void cp_wait() {
    asm volatile("cp.async.wait_group %0;\n" :: "n"(N));
}

__device__ __forceinline__ uint32_t f2tf32(float x) {
    uint32_t r;
    asm("cvt.rna.tf32.f32 %0, %1;" : "=r"(r) : "f"(x));
    return r;
}

// ---------------------------------------------------------------------------
// Single persistent kernel:
//   Phase 1: split-K tf32 tensor GEMM (block tile 128x32, 2-stage cp.async)
//   grid-wide ticket barrier
//   Phase 2: CTA b -> fused prep (u = input_b . A -> v) + split-K reduce
//            + bias + rank-2 epilogue for output row b
// ---------------------------------------------------------------------------
__global__ __launch_bounds__(256) void fused_kernel(
        const float* __restrict__ input,
        const float* __restrict__ codes,
        const float* __restrict__ weight,
        const float* __restrict__ A,
        const float* __restrict__ Bm,
        const float* __restrict__ bias,
        const float* __restrict__ bctx,
        float* __restrict__ out) {
    __shared__ float sA[2][128][KT + 4];   // stride 36, conflict-free
    __shared__ float sB[2][KT][BN + 8];    // stride 40, conflict-free
    __shared__ float s_red[8][2];          // phase-2 warp partials

    int tid = threadIdx.x;
    int bid = blockIdx.x;

    // ======================= Phase 1: GEMM =======================
    {
        int nb = (bid & 31) * BN;
        int ks = bid >> 5;
        int k_base = ks * KCHUNK;

        int wid = tid >> 5, lane = tid & 31;
        int wm = wid & 3, wn = wid >> 2;
        int m_base = wm * 32, n_base = wn * 16;
        int g = lane >> 2, q = lane & 3;

        int a_row = tid >> 3, a_c4 = (tid & 7) * 4;
        int b_row = tid >> 3, b_c4 = (tid & 7) * 4;

        float acc[2][2][4];
        #pragma unroll
        for (int mi = 0; mi < 2; mi++)
            #pragma unroll
            for (int ni = 0; ni < 2; ni++)
                #pragma unroll
                for (int r = 0; r < 4; r++) acc[mi][ni][r] = 0.f;

        // prefetch stage 0
        {
            int k0 = k_base;
            #pragma unroll
            for (int t = 0; t < 4; t++) {
                int row = a_row + t * 32;
                cp_async16(&sA[0][row][a_c4], input + row * K_F + k0 + a_c4);
            }
            cp_async16(&sB[0][b_row][b_c4], weight + (k0 + b_row) * N_F + nb + b_c4);
            cp_commit();
        }

        for (int s = 0; s < NITER; s++) {
            int buf = s & 1;
            if (s + 1 < NITER) {
                int k0 = k_base + (s + 1) * KT;
                int nbuf = (s + 1) & 1;
                #pragma unroll
                for (int t = 0; t < 4; t++) {
                    int row = a_row + t * 32;
                    cp_async16(&sA[nbuf][row][a_c4], input + row * K_F + k0 + a_c4);
                }
                cp_async16(&sB[nbuf][b_row][b_c4],
                           weight + (k0 + b_row) * N_F + nb + b_c4);
                cp_commit();
                cp_wait<1>();
            } else {
                cp_wait<0>();
            }
            __syncthreads();

            #pragma unroll
            for (int kk = 0; kk < KT; kk += 8) {
                uint32_t afr[2][4], bfr[2][2];
                #pragma unroll
                for (int mi = 0; mi < 2; mi++) {
                    int r0 = m_base + mi * 16 + g;
                    afr[mi][0] = f2tf32(sA[buf][r0    ][kk + q    ]);
                    afr[mi][1] = f2tf32(sA[buf][r0 + 8][kk + q    ]);
                    afr[mi][2] = f2tf32(sA[buf][r0    ][kk + q + 4]);
                    afr[mi][3] = f2tf32(sA[buf][r0 + 8][kk + q + 4]);
                }
                #pragma unroll
                for (int ni = 0; ni < 2; ni++) {
                    int c0 = n_base + ni * 8 + g;
                    bfr[ni][0] = f2tf32(sB[buf][kk + q    ][c0]);
                    bfr[ni][1] = f2tf32(sB[buf][kk + q + 4][c0]);
                }
                #pragma unroll
                for (int mi = 0; mi < 2; mi++)
                    #pragma unroll
                    for (int ni = 0; ni < 2; ni++) {
                        asm volatile(
                            "mma.sync.aligned.m16n8k8.row.col.f32.tf32.tf32.f32 "
                            "{%0,%1,%2,%3}, {%4,%5,%6,%7}, {%8,%9}, {%0,%1,%2,%3};\n"
                            : "+f"(acc[mi][ni][0]), "+f"(acc[mi][ni][1]),
                              "+f"(acc[mi][ni][2]), "+f"(acc[mi][ni][3])
                            : "r"(afr[mi][0]), "r"(afr[mi][1]),
                              "r"(afr[mi][2]), "r"(afr[mi][3]),
                              "r"(bfr[ni][0]), "r"(bfr[ni][1]));
                    }
            }
            __syncthreads();
        }

        // write split-K partials
        float* part = g_partial + ks * (M_B * N_F);
        #pragma unroll
        for (int mi = 0; mi < 2; mi++)
            #pragma unroll
            for (int ni = 0; ni < 2; ni++) {
                int row = m_base + mi * 16 + g;
                int col = nb + n_base + ni * 8 + q * 2;
                part[row * N_F + col]           = acc[mi][ni][0];
                part[row * N_F + col + 1]       = acc[mi][ni][1];
                part[(row + 8) * N_F + col]     = acc[mi][ni][2];
                part[(row + 8) * N_F + col + 1] = acc[mi][ni][3];
            }
    }

    // ================== grid-wide ticket barrier ==================
    __threadfence();
    __syncthreads();
    if (tid == 0) {
        unsigned int ticket = atomicAdd(&g_cnt, 1u);
        unsigned int target = (ticket / GRID + 1u) * GRID;
        while (*((volatile unsigned int*)&g_cnt) < target) { }
    }
    __syncthreads();
    __threadfence();

    // ======================= Phase 2: fused prep + reduce + epilogue =======
    {
        int b = bid;   // one CTA per batch row
        // --- prep: u = input_b . A (thread t owns input[b, 4t..4t+3]) ---
        float4 x = *reinterpret_cast<const float4*>(input + b * K_F + tid * 4);
        const float2* A2 = reinterpret_cast<const float2*>(A);
        float2 a0 = A2[tid * 4 + 0];
        float2 a1 = A2[tid * 4 + 1];
        float2 a2 = A2[tid * 4 + 2];
        float2 a3 = A2[tid * 4 + 3];
        float p0 = x.x * a0.x + x.y * a1.x + x.z * a2.x + x.w * a3.x;
        float p1 = x.x * a0.y + x.y * a1.y + x.z * a2.y + x.w * a3.y;
        #pragma unroll
        for (int off = 16; off > 0; off >>= 1) {
            p0 += __shfl_xor_sync(0xFFFFFFFFu, p0, off);
            p1 += __shfl_xor_sync(0xFFFFFFFFu, p1, off);
        }
        int w = tid >> 5, lane = tid & 31;
        if (lane == 0) { s_red[w][0] = p0; s_red[w][1] = p1; }
        __syncthreads();
        float u0 = 0.f, u1 = 0.f;
        #pragma unroll
        for (int i = 0; i < 8; i++) { u0 += s_red[i][0]; u1 += s_red[i][1]; }

        float c00 = codes[b * 4 + 0], c01 = codes[b * 4 + 1];
        float c10 = codes[b * 4 + 2], c11 = codes[b * 4 + 3];
        float v0 = u0 * c00 + u1 * c10;
        float v1 = u0 * c01 + u1 * c11;
        float d0 = c00, d1 = c11;

        // --- reduce + epilogue: thread t owns out[b, 4t..4t+3] ---
        int j4 = tid * 4;
        float4 s = *reinterpret_cast<const float4*>(&g_partial[b * N_F + j4]);
        #pragma unroll
        for (int ks = 1; ks < KSPLIT; ks++) {
            float4 p = *reinterpret_cast<const float4*>(
                &g_partial[ks * (M_B * N_F) + b * N_F + j4]);
            s.x += p.x; s.y += p.y; s.z += p.z; s.w += p.w;
        }
        float4 bi = *reinterpret_cast<const float4*>(bias + j4);
        float4 B0 = *reinterpret_cast<const float4*>(Bm + j4);
        float4 B1 = *reinterpret_cast<const float4*>(Bm + N_F + j4);
        float4 e0 = *reinterpret_cast<const float4*>(bctx + j4);
        float4 e1 = *reinterpret_cast<const float4*>(bctx + N_F + j4);

        float4 o;
        o.x = s.x + bi.x + v0 * B0.x + v1 * B1.x + d0 * e0.x + d1 * e1.x;
        o.y = s.y + bi.y + v0 * B0.y + v1 * B1.y + d0 * e0.y + d1 * e1.y;
        o.z = s.z + bi.z + v0 * B0.z + v1 * B1.z + d0 * e0.z + d1 * e1.z;
        o.w = s.w + bi.w + v0 * B0.w + v1 * B1.w + d0 * e0.w + d1 * e1.w;
        *reinterpret_cast<float4*>(out + b * N_F + j4) = o;
    }
}

extern "C" void kernel_launch(void* const* d_in, const int* in_sizes, int n_in,
                              void* d_out, int out_size) {
    const float* input  = (const float*)d_in[0];
    const float* codes  = (const float*)d_in[1];
    const float* weight = (const float*)d_in[2];
    const float* A      = (const float*)d_in[3];
    const float* Bm     = (const float*)d_in[4];
    const float* bias   = (const float*)d_in[5];
    const float* bctx   = (const float*)d_in[6];
    float* out = (float*)d_out;

    fused_kernel<<<GRID, 256>>>(input, codes, weight, A, Bm, bias, bctx, out);
}